// round 12
// baseline (speedup 1.0000x reference)
#include <cuda_runtime.h>
#include <cuda_fp16.h>
#include <cstdint>

// Problem constants
#define BB 4096
#define OO 11008
#define KK 4096
#define GG 32               // K / group_size (one group = 128 k = 128 bytes int8)

// GEMM tiling: CTA = 128M x 128N; cols 0..79 tensor warps, 80..127 dp4a warps
#define MT 128
#define NT 128
#define MTILES (BB / MT)    // 32
#define NTILES (OO / NT)    // 86
#define STAGES 4
#define STAGE_BYTES 32768   // (128 A rows + 128 B rows) * 128 k-bytes
#define SCALE_BYTES 32768   // a-scales 16KB + w-scales 16KB (f32)
#define SMEM_TOTAL (SCALE_BYTES + STAGES * STAGE_BYTES)   // 163840
#define NTHREADS 512
#define CT 80               // tensor columns
#define NTW 5               // n8-tiles per tensor warp (40 cols / 8)

// plain row-major int8 scratch
__device__ __align__(1024) uint8_t g_xq[(size_t)BB * KK];  // 16.8 MB
__device__ __align__(1024) uint8_t g_wq[(size_t)OO * KK];  // 45 MB

// ---------------------------------------------------------------- helpers
__device__ __forceinline__ uint32_t smem_u32(const void* p) {
    uint32_t a;
    asm("{ .reg .u64 t; cvta.to.shared.u64 t, %1; cvt.u32.u64 %0, t; }" : "=r"(a) : "l"(p));
    return a;
}
__device__ __forceinline__ void cp16(uint32_t s, const void* g) {
    asm volatile("cp.async.cg.shared.global [%0], [%1], 16;" :: "r"(s), "l"(g));
}
__device__ __forceinline__ void cp_commit() {
    asm volatile("cp.async.commit_group;" ::: "memory");
}
__device__ __forceinline__ void cp_wait2() {
    asm volatile("cp.async.wait_group 2;" ::: "memory");
}
__device__ __forceinline__ void mma_s8(int* c, const uint32_t* a, const uint32_t* b) {
    asm volatile(
        "mma.sync.aligned.m16n8k32.row.col.s32.s8.s8.s32 "
        "{%0,%1,%2,%3}, {%4,%5,%6,%7}, {%8,%9}, {%0,%1,%2,%3};"
        : "+r"(c[0]), "+r"(c[1]), "+r"(c[2]), "+r"(c[3])
        : "r"(a[0]), "r"(a[1]), "r"(a[2]), "r"(a[3]), "r"(b[0]), "r"(b[1]));
}

// ---------------------------------------------------------------- prepack (fused)
#define TOTX (BB * KK / 2)
#define TOTW (OO * KK / 2)
__global__ void __launch_bounds__(256) prepack_all(const int* __restrict__ px,
                                                   const int* __restrict__ pw) {
    int i = blockIdx.x * blockDim.x + threadIdx.x;
    const int* src;
    char2* dst;
    int j;
    if (i < TOTX) { src = px; dst = (char2*)g_xq; j = i; }
    else if (i < TOTX + TOTW) { src = pw; dst = (char2*)g_wq; j = i - TOTX; }
    else return;
    int v = src[j];
    int lo = ((v & 15) ^ 8) - 8;
    int hi = (((v >> 4) & 15) ^ 8) - 8;
    dst[j] = make_char2((char)lo, (char)hi);
}

// ---------------------------------------------------------------- GEMM (warp-specialized hybrid)
// smem per stage: A rows 0..127 then B rows 0..127, each row 128 bytes.
// row layout: eight 16B chunks, chunk c stored at phys = c ^ (row & 7).
__global__ void __launch_bounds__(NTHREADS, 1)
gemm_kernel(const float* __restrict__ a_scale, const float* __restrict__ w_scale,
            const float* __restrict__ bias, float* __restrict__ out) {
    extern __shared__ uint8_t smem[];
    float* s_as = (float*)smem;                    // [32 groups][128 rows]
    float* s_ws = (float*)(smem + 16384);          // [32 groups][128 cols]
    uint8_t* s_data = smem + SCALE_BYTES;

    int tid = threadIdx.x, wid = tid >> 5, lane = tid & 31;
    int g8 = lane >> 2, tig = lane & 3;

    // supertile rasterization (8 m-tiles per group) for L2 reuse
    int bid = blockIdx.x;
    int grp = bid / (8 * NTILES);
    int rem = bid - grp * (8 * NTILES);
    int mt = grp * 8 + (rem & 7);
    int nt = rem >> 3;
    int m0 = mt * MT, n0 = nt * NT;

    // stage scales once per CTA, transposed to [group][row]
    #pragma unroll 2
    for (int i = tid; i < 4096; i += NTHREADS) {
        int g = i >> 7, r = i & 127;
        s_as[i] = __ldg(a_scale + (size_t)(m0 + r) * GG + g);
        s_ws[i] = __ldg(w_scale + (size_t)(n0 + r) * GG + g);
    }

    const uint8_t* gA = g_xq + (size_t)m0 * KK;
    const uint8_t* gB = g_wq + (size_t)n0 * KK;

    // loader: 2048 x 16B per stage, 4 cp16 per thread
#define LOAD_STAGE(slot, g_)                                                       \
    do {                                                                           \
        uint32_t st_ = smem_u32(s_data + (slot) * STAGE_BYTES);                    \
        _Pragma("unroll")                                                          \
        for (int it_ = 0; it_ < 4; it_++) {                                        \
            int j_ = tid + NTHREADS * it_;                                         \
            int r_ = (j_ >> 3) & 127;                                              \
            int c_ = j_ & 7;                                                       \
            int phys_ = c_ ^ (r_ & 7);                                             \
            uint32_t sa_ = st_ + (uint32_t)((j_ >> 10) * 16384 + r_ * 128 + phys_ * 16); \
            const uint8_t* gp_ = ((j_ >> 10) ? gB : gA) + (size_t)r_ * KK + (g_) * 128 + c_ * 16; \
            cp16(sa_, gp_);                                                        \
        }                                                                          \
        cp_commit();                                                               \
    } while (0)

    LOAD_STAGE(0, 0);
    LOAD_STAGE(1, 1);
    LOAD_STAGE(2, 2);

    if (wid < 8) {
        // ================= TENSOR warps: cols 0..79 =================
        // warp grid 4M x 2N, warp tile 32M x 40N (5 n8-tiles)
        int warp_m = (wid & 3) * 32;
        int warp_n = (wid >> 2) * 40;

        float accf[2][NTW][4];
        #pragma unroll
        for (int a = 0; a < 2; a++)
            #pragma unroll
            for (int b = 0; b < NTW; b++)
                #pragma unroll
                for (int c = 0; c < 4; c++) accf[a][b][c] = 0.f;

        for (int g = 0; g < GG; g++) {
            cp_wait2();
            __syncthreads();
            if (g + 3 < GG) LOAD_STAGE((g + 3) & 3, g + 3);

            const uint8_t* stA = s_data + (g & 3) * STAGE_BYTES;
            const uint8_t* stB = stA + 16384;

            int accs[2][NTW][4];
            #pragma unroll
            for (int a = 0; a < 2; a++)
                #pragma unroll
                for (int b = 0; b < NTW; b++)
                    #pragma unroll
                    for (int c = 0; c < 4; c++) accs[a][b][c] = 0;

            #pragma unroll
            for (int ks = 0; ks < 4; ks++) {
                int off0 = (((2 * ks)     ^ g8) << 4) + tig * 4;   // k = ks*32 + tig*4
                int off1 = (((2 * ks + 1) ^ g8) << 4) + tig * 4;   // + 16
                uint32_t af[2][4];
                #pragma unroll
                for (int m = 0; m < 2; m++) {
                    const uint8_t* p0 = stA + (warp_m + m * 16 + g8) * 128;
                    af[m][0] = *(const uint32_t*)(p0 + off0);
                    af[m][1] = *(const uint32_t*)(p0 + 1024 + off0);   // +8 rows
                    af[m][2] = *(const uint32_t*)(p0 + off1);
                    af[m][3] = *(const uint32_t*)(p0 + 1024 + off1);
                }
                uint32_t bf[NTW][2];
                #pragma unroll
                for (int n = 0; n < NTW; n++) {
                    const uint8_t* pb = stB + (warp_n + n * 8 + g8) * 128;
                    bf[n][0] = *(const uint32_t*)(pb + off0);
                    bf[n][1] = *(const uint32_t*)(pb + off1);
                }
                #pragma unroll
                for (int m = 0; m < 2; m++)
                    #pragma unroll
                    for (int n = 0; n < NTW; n++)
                        mma_s8(accs[m][n], af[m], bf[n]);
            }

            float rs[4], cs[2 * NTW];
            #pragma unroll
            for (int m = 0; m < 2; m++) {
                int r = warp_m + m * 16 + g8;
                rs[2 * m]     = s_as[g * 128 + r];
                rs[2 * m + 1] = s_as[g * 128 + r + 8];
            }
            #pragma unroll
            for (int n = 0; n < NTW; n++) {
                int c = warp_n + n * 8 + tig * 2;
                cs[2 * n]     = s_ws[g * 128 + c];
                cs[2 * n + 1] = s_ws[g * 128 + c + 1];
            }
            #pragma unroll
            for (int m = 0; m < 2; m++)
                #pragma unroll
                for (int n = 0; n < NTW; n++) {
                    accf[m][n][0] += (float)accs[m][n][0] * (rs[2 * m]     * cs[2 * n]);
                    accf[m][n][1] += (float)accs[m][n][1] * (rs[2 * m]     * cs[2 * n + 1]);
                    accf[m][n][2] += (float)accs[m][n][2] * (rs[2 * m + 1] * cs[2 * n]);
                    accf[m][n][3] += (float)accs[m][n][3] * (rs[2 * m + 1] * cs[2 * n + 1]);
                }
        }

        // epilogue (cols n0 .. n0+79)
        #pragma unroll
        for (int m = 0; m < 2; m++)
            #pragma unroll
            for (int n = 0; n < NTW; n++) {
                int row = m0 + warp_m + m * 16 + g8;
                int col = n0 + warp_n + n * 8 + tig * 2;
                __half hb0 = __float2half_rn(__ldg(bias + col));
                __half hb1 = __float2half_rn(__ldg(bias + col + 1));
                float2 lo, hi;
                lo.x = __half2float(__hadd(__float2half_rn(accf[m][n][0]), hb0));
                lo.y = __half2float(__hadd(__float2half_rn(accf[m][n][1]), hb1));
                hi.x = __half2float(__hadd(__float2half_rn(accf[m][n][2]), hb0));
                hi.y = __half2float(__hadd(__float2half_rn(accf[m][n][3]), hb1));
                *(float2*)(out + (size_t)row * OO + col) = lo;
                *(float2*)(out + (size_t)(row + 8) * OO + col) = hi;
            }
    } else {
        // ================= DP4A warps: cols 80..127 =================
        int dtid = tid - 256;                 // 0..255
        int dr0 = (dtid >> 3) * 4;            // row base 0..124
        int dc0 = CT + (dtid & 7) * 6;        // col base 80..122 (6 cols per thread)
        int rot = 2 * (lane & 7);             // k8 rotation: distinct chunks per lane-octet

        float dfac[4][6];
        #pragma unroll
        for (int i = 0; i < 4; i++)
            #pragma unroll
            for (int j = 0; j < 6; j++) dfac[i][j] = 0.f;

        for (int g = 0; g < GG; g++) {
            cp_wait2();
            __syncthreads();
            if (g + 3 < GG) LOAD_STAGE((g + 3) & 3, g + 3);

            const uint8_t* stA = s_data + (g & 3) * STAGE_BYTES;
            const uint8_t* stB = stA + 16384;

            int dacc[4][6];
            #pragma unroll
            for (int i = 0; i < 4; i++)
                #pragma unroll
                for (int j = 0; j < 6; j++) dacc[i][j] = 0;

            #pragma unroll
            for (int st = 0; st < 16; st++) {
                int s = (st + rot) & 15;       // k8 index (8 k-values = 8 bytes)
                int ch = s >> 1, sub = (s & 1) * 8;
                uint2 a2[4];
                #pragma unroll
                for (int i = 0; i < 4; i++) {
                    int r = dr0 + i;
                    a2[i] = *(const uint2*)(stA + r * 128 + ((ch ^ (r & 7)) << 4) + sub);
                }
                uint2 b2[6];
                #pragma unroll
                for (int j = 0; j < 6; j++) {
                    int c = dc0 + j;
                    b2[j] = *(const uint2*)(stB + c * 128 + ((ch ^ (c & 7)) << 4) + sub);
                }
                #pragma unroll
                for (int i = 0; i < 4; i++)
                    #pragma unroll
                    for (int j = 0; j < 6; j++) {
                        dacc[i][j] = __dp4a((int)a2[i].x, (int)b2[j].x, dacc[i][j]);
                        dacc[i][j] = __dp4a((int)a2[i].y, (int)b2[j].y, dacc[i][j]);
                    }
            }

            float ra[4], cb[6];
            #pragma unroll
            for (int i = 0; i < 4; i++) ra[i] = s_as[g * 128 + dr0 + i];
            #pragma unroll
            for (int j = 0; j < 6; j++) cb[j] = s_ws[g * 128 + dc0 + j];
            #pragma unroll
            for (int i = 0; i < 4; i++)
                #pragma unroll
                for (int j = 0; j < 6; j++)
                    dfac[i][j] += (float)dacc[i][j] * (ra[i] * cb[j]);
        }

        // epilogue (cols n0+80 .. n0+127), 3 x float2 per row
        #pragma unroll
        for (int i = 0; i < 4; i++) {
            int row = m0 + dr0 + i;
            int col = n0 + dc0;
            float vv[6];
            #pragma unroll
            for (int j = 0; j < 6; j++) {
                __half hb = __float2half_rn(__ldg(bias + col + j));
                vv[j] = __half2float(__hadd(__float2half_rn(dfac[i][j]), hb));
            }
            *(float2*)(out + (size_t)row * OO + col)     = make_float2(vv[0], vv[1]);
            *(float2*)(out + (size_t)row * OO + col + 2) = make_float2(vv[2], vv[3]);
            *(float2*)(out + (size_t)row * OO + col + 4) = make_float2(vv[4], vv[5]);
        }
    }
}

// ---------------------------------------------------------------- host
extern "C" void kernel_launch(void* const* d_in, const int* in_sizes, int n_in,
                              void* d_out, int out_size) {
    const int*   x        = (const int*)d_in[0];
    const float* a_scale  = (const float*)d_in[1];   // fp16 in reference -> float32 in harness
    const int*   w_packed = (const int*)d_in[2];
    const float* w_scale  = (const float*)d_in[3];
    const float* bias     = (const float*)d_in[4];
    float*       out      = (float*)d_out;

    int tot = TOTX + TOTW;
    prepack_all<<<(tot + 255) / 256, 256>>>(x, w_packed);

    static bool attr_set = false;
    if (!attr_set) {
        cudaFuncSetAttribute(gemm_kernel, cudaFuncAttributeMaxDynamicSharedMemorySize, SMEM_TOTAL);
        attr_set = true;
    }
    gemm_kernel<<<MTILES * NTILES, NTHREADS, SMEM_TOTAL>>>(a_scale, w_scale, bias, out);
}

// round 13
// speedup vs baseline: 1.5338x; 1.5338x over previous
#include <cuda_runtime.h>
#include <cuda_fp16.h>
#include <cstdint>

// Problem constants
#define BB 4096
#define OO 11008
#define KK 4096
#define GG 32               // K / group_size (group = 128 k)

// GEMM tiling: CTA 128M x 128N, 16 warps, warp tile 32x32, fp16 HMMA
#define MT 128
#define NT 128
#define MTILES (BB / MT)    // 32
#define NTILES (OO / NT)    // 86
#define STAGES 4
#define NST 64              // pipeline stages of 64 k each (2 per scale group)
#define STAGE_BYTES 32768   // (128 A rows + 128 B rows) * 64k * 2B = 16KB + 16KB
#define SCALE_BYTES 32768   // a-scales 16KB + w-scales 16KB (f32)
#define SMEM_TOTAL (SCALE_BYTES + STAGES * STAGE_BYTES)   // 163840
#define NTHREADS 512

// fp16 scratch, row-major
__device__ __align__(1024) __half g_xh[(size_t)BB * KK];  // 32 MB
__device__ __align__(1024) __half g_wh[(size_t)OO * KK];  // 90 MB

// ---------------------------------------------------------------- helpers
__device__ __forceinline__ uint32_t smem_u32(const void* p) {
    uint32_t a;
    asm("{ .reg .u64 t; cvta.to.shared.u64 t, %1; cvt.u32.u64 %0, t; }" : "=r"(a) : "l"(p));
    return a;
}
__device__ __forceinline__ void cp16(uint32_t s, const void* g) {
    asm volatile("cp.async.cg.shared.global [%0], [%1], 16;" :: "r"(s), "l"(g));
}
__device__ __forceinline__ void cp_commit() {
    asm volatile("cp.async.commit_group;" ::: "memory");
}
__device__ __forceinline__ void cp_wait2() {
    asm volatile("cp.async.wait_group 2;" ::: "memory");
}
// m16n8k16 fp16 x fp16 -> f32 accumulate
__device__ __forceinline__ void mma_f16(float* c, const uint32_t* a, const uint32_t* b) {
    asm volatile(
        "mma.sync.aligned.m16n8k16.row.col.f32.f16.f16.f32 "
        "{%0,%1,%2,%3}, {%4,%5,%6,%7}, {%8,%9}, {%0,%1,%2,%3};"
        : "+f"(c[0]), "+f"(c[1]), "+f"(c[2]), "+f"(c[3])
        : "r"(a[0]), "r"(a[1]), "r"(a[2]), "r"(a[3]), "r"(b[0]), "r"(b[1]));
}

// ---------------------------------------------------------------- prepack (fused, -> fp16)
#define TOTX (BB * KK / 2)
#define TOTW (OO * KK / 2)
__global__ void __launch_bounds__(256) prepack_all(const int* __restrict__ px,
                                                   const int* __restrict__ pw) {
    int i = blockIdx.x * blockDim.x + threadIdx.x;
    const int* src;
    uint32_t* dst;
    int j;
    if (i < TOTX) { src = px; dst = (uint32_t*)g_xh; j = i; }
    else if (i < TOTX + TOTW) { src = pw; dst = (uint32_t*)g_wh; j = i - TOTX; }
    else return;
    int v = src[j];
    int lo = ((v & 15) ^ 8) - 8;
    int hi = (((v >> 4) & 15) ^ 8) - 8;
    __half2 h = __halves2half2(__int2half_rn(lo), __int2half_rn(hi));
    dst[j] = *(uint32_t*)&h;
}

// ---------------------------------------------------------------- GEMM (fp16 HMMA)
// smem per stage: A rows 0..127 then B rows 0..127, each row = 64 k fp16 = 128 bytes.
// row layout: eight 16B chunks, chunk c stored at phys = c ^ (row & 7).
__global__ void __launch_bounds__(NTHREADS, 1)
gemm_kernel(const float* __restrict__ a_scale, const float* __restrict__ w_scale,
            const float* __restrict__ bias, float* __restrict__ out) {
    extern __shared__ uint8_t smem[];
    float* s_as = (float*)smem;                    // [32 groups][128 rows]
    float* s_ws = (float*)(smem + 16384);          // [32 groups][128 cols]
    uint8_t* s_data = smem + SCALE_BYTES;

    int tid = threadIdx.x, wid = tid >> 5, lane = tid & 31;
    int g8 = lane >> 2, tig = lane & 3;
    // warp grid 4M x 4N, warp tile 32M x 32N
    int warp_m = (wid & 3) * 32;
    int warp_n = (wid >> 2) * 32;

    // supertile rasterization (8 m-tiles per group) for L2 reuse
    int bid = blockIdx.x;
    int grp = bid / (8 * NTILES);
    int rem = bid - grp * (8 * NTILES);
    int mt = grp * 8 + (rem & 7);
    int nt = rem >> 3;
    int m0 = mt * MT, n0 = nt * NT;

    // stage scales once per CTA, transposed to [group][row]
    #pragma unroll 2
    for (int i = tid; i < 4096; i += NTHREADS) {
        int g = i >> 7, r = i & 127;
        s_as[i] = __ldg(a_scale + (size_t)(m0 + r) * GG + g);
        s_ws[i] = __ldg(w_scale + (size_t)(n0 + r) * GG + g);
    }

    const uint8_t* gA = (const uint8_t*)g_xh + (size_t)m0 * KK * 2;
    const uint8_t* gB = (const uint8_t*)g_wh + (size_t)n0 * KK * 2;

    // loader: 2048 x 16B per stage (stage s64 covers k bytes [s64*128, +128))
#define LOAD_STAGE(slot, s64)                                                      \
    do {                                                                           \
        uint32_t st_ = smem_u32(s_data + (slot) * STAGE_BYTES);                    \
        _Pragma("unroll")                                                          \
        for (int it_ = 0; it_ < 4; it_++) {                                        \
            int j_ = tid + NTHREADS * it_;                                         \
            int r_ = (j_ >> 3) & 127;                                              \
            int c_ = j_ & 7;                                                       \
            int phys_ = c_ ^ (r_ & 7);                                             \
            uint32_t sa_ = st_ + (uint32_t)((j_ >> 10) * 16384 + r_ * 128 + phys_ * 16); \
            const uint8_t* gp_ = ((j_ >> 10) ? gB : gA) + (size_t)r_ * (KK * 2) + (s64) * 128 + c_ * 16; \
            cp16(sa_, gp_);                                                        \
        }                                                                          \
        cp_commit();                                                               \
    } while (0)

    LOAD_STAGE(0, 0);
    LOAD_STAGE(1, 1);
    LOAD_STAGE(2, 2);

    float accf[2][4][4];    // running rescaled accumulator
    #pragma unroll
    for (int a = 0; a < 2; a++)
        #pragma unroll
        for (int b = 0; b < 4; b++)
            #pragma unroll
            for (int c = 0; c < 4; c++) accf[a][b][c] = 0.f;

    float accg[2][4][4];    // per-group exact sum (f32, HMMA accumulate)

    for (int s = 0; s < NST; s++) {
        if ((s & 1) == 0) {
            #pragma unroll
            for (int a = 0; a < 2; a++)
                #pragma unroll
                for (int b = 0; b < 4; b++)
                    #pragma unroll
                    for (int c = 0; c < 4; c++) accg[a][b][c] = 0.f;
        }

        cp_wait2();
        __syncthreads();
        if (s + 3 < NST) LOAD_STAGE((s + 3) & 3, s + 3);

        const uint8_t* stA = s_data + (s & 3) * STAGE_BYTES;
        const uint8_t* stB = stA + 16384;

        // 4 k16 steps per 64k stage; k16 block = 32 bytes = chunks (2ks, 2ks+1)
        #pragma unroll
        for (int ks = 0; ks < 4; ks++) {
            int off0 = (((2 * ks)     ^ g8) << 4) + tig * 4;   // k = 16ks + 2tig (+1)
            int off1 = (((2 * ks + 1) ^ g8) << 4) + tig * 4;   // k = 16ks + 8 + 2tig (+1)
            uint32_t af[2][4];
            #pragma unroll
            for (int m = 0; m < 2; m++) {
                const uint8_t* p0 = stA + (warp_m + m * 16 + g8) * 128;
                af[m][0] = *(const uint32_t*)(p0 + off0);          // (row g,   k0..1)
                af[m][1] = *(const uint32_t*)(p0 + 1024 + off0);   // (row g+8, k0..1)
                af[m][2] = *(const uint32_t*)(p0 + off1);          // (row g,   k8..9)
                af[m][3] = *(const uint32_t*)(p0 + 1024 + off1);   // (row g+8, k8..9)
            }
            uint32_t bf[4][2];
            #pragma unroll
            for (int n = 0; n < 4; n++) {
                const uint8_t* pb = stB + (warp_n + n * 8 + g8) * 128;
                bf[n][0] = *(const uint32_t*)(pb + off0);
                bf[n][1] = *(const uint32_t*)(pb + off1);
            }
            #pragma unroll
            for (int m = 0; m < 2; m++)
                #pragma unroll
                for (int n = 0; n < 4; n++)
                    mma_f16(accg[m][n], af[m], bf[n]);
        }

        if (s & 1) {
            // end of group g = s>>1: exact per-group rescale into running acc
            int g = s >> 1;
            float rs[4], cs[8];
            #pragma unroll
            for (int m = 0; m < 2; m++) {
                int r = warp_m + m * 16 + g8;
                rs[2 * m]     = s_as[g * 128 + r];
                rs[2 * m + 1] = s_as[g * 128 + r + 8];
            }
            #pragma unroll
            for (int n = 0; n < 4; n++) {
                int c = warp_n + n * 8 + tig * 2;
                cs[2 * n]     = s_ws[g * 128 + c];
                cs[2 * n + 1] = s_ws[g * 128 + c + 1];
            }
            #pragma unroll
            for (int m = 0; m < 2; m++)
                #pragma unroll
                for (int n = 0; n < 4; n++) {
                    accf[m][n][0] += accg[m][n][0] * (rs[2 * m]     * cs[2 * n]);
                    accf[m][n][1] += accg[m][n][1] * (rs[2 * m]     * cs[2 * n + 1]);
                    accf[m][n][2] += accg[m][n][2] * (rs[2 * m + 1] * cs[2 * n]);
                    accf[m][n][3] += accg[m][n][3] * (rs[2 * m + 1] * cs[2 * n + 1]);
                }
        }
    }

    // epilogue: emulate reference fp16 rounding, store upcast float32
    #pragma unroll
    for (int m = 0; m < 2; m++)
        #pragma unroll
        for (int n = 0; n < 4; n++) {
            int row = m0 + warp_m + m * 16 + g8;
            int col = n0 + warp_n + n * 8 + tig * 2;
            __half hb0 = __float2half_rn(__ldg(bias + col));
            __half hb1 = __float2half_rn(__ldg(bias + col + 1));
            float2 lo, hi;
            lo.x = __half2float(__hadd(__float2half_rn(accf[m][n][0]), hb0));
            lo.y = __half2float(__hadd(__float2half_rn(accf[m][n][1]), hb1));
            hi.x = __half2float(__hadd(__float2half_rn(accf[m][n][2]), hb0));
            hi.y = __half2float(__hadd(__float2half_rn(accf[m][n][3]), hb1));
            *(float2*)(out + (size_t)row * OO + col) = lo;
            *(float2*)(out + (size_t)(row + 8) * OO + col) = hi;
        }
}

// ---------------------------------------------------------------- host
extern "C" void kernel_launch(void* const* d_in, const int* in_sizes, int n_in,
                              void* d_out, int out_size) {
    const int*   x        = (const int*)d_in[0];
    const float* a_scale  = (const float*)d_in[1];   // fp16 in reference -> float32 in harness
    const int*   w_packed = (const int*)d_in[2];
    const float* w_scale  = (const float*)d_in[3];
    const float* bias     = (const float*)d_in[4];
    float*       out      = (float*)d_out;

    int tot = TOTX + TOTW;
    prepack_all<<<(tot + 255) / 256, 256>>>(x, w_packed);

    static bool attr_set = false;
    if (!attr_set) {
        cudaFuncSetAttribute(gemm_kernel, cudaFuncAttributeMaxDynamicSharedMemorySize, SMEM_TOTAL);
        attr_set = true;
    }
    gemm_kernel<<<MTILES * NTILES, NTHREADS, SMEM_TOTAL>>>(a_scale, w_scale, bias, out);
}

// round 14
// speedup vs baseline: 1.7672x; 1.1522x over previous
#include <cuda_runtime.h>
#include <cuda_fp16.h>
#include <cstdint>

// Problem constants
#define BB 4096
#define OO 11008
#define KK 4096
#define GG 32               // K / group_size (group = 128 k = 256 bytes fp16)

// GEMM tiling: CTA 128M x 128N, 16 warps, warp tile 32x32, fp16 HMMA
#define MT 128
#define NT 128
#define MTILES (BB / MT)    // 32
#define NTILES (OO / NT)    // 86
#define STAGES 3
#define STAGE_BYTES 65536   // (128 A rows + 128 B rows) * 128k * 2B
#define SCALE_BYTES 16384   // fp16 scales: 8KB a + 8KB w
#define SMEM_TOTAL (SCALE_BYTES + STAGES * STAGE_BYTES)   // 212992
#define NTHREADS 512

// fp16 scratch, row-major
__device__ __align__(1024) __half g_xh[(size_t)BB * KK];  // 32 MB
__device__ __align__(1024) __half g_wh[(size_t)OO * KK];  // 90 MB

// ---------------------------------------------------------------- helpers
__device__ __forceinline__ uint32_t smem_u32(const void* p) {
    uint32_t a;
    asm("{ .reg .u64 t; cvta.to.shared.u64 t, %1; cvt.u32.u64 %0, t; }" : "=r"(a) : "l"(p));
    return a;
}
__device__ __forceinline__ void cp16(uint32_t s, const void* g) {
    asm volatile("cp.async.cg.shared.global [%0], [%1], 16;" :: "r"(s), "l"(g));
}
__device__ __forceinline__ void cp_commit() {
    asm volatile("cp.async.commit_group;" ::: "memory");
}
__device__ __forceinline__ void cp_wait1() {
    asm volatile("cp.async.wait_group 1;" ::: "memory");
}
// m16n8k16 fp16 x fp16 -> f32 accumulate
__device__ __forceinline__ void mma_f16(float* c, const uint32_t* a, const uint32_t* b) {
    asm volatile(
        "mma.sync.aligned.m16n8k16.row.col.f32.f16.f16.f32 "
        "{%0,%1,%2,%3}, {%4,%5,%6,%7}, {%8,%9}, {%0,%1,%2,%3};"
        : "+f"(c[0]), "+f"(c[1]), "+f"(c[2]), "+f"(c[3])
        : "r"(a[0]), "r"(a[1]), "r"(a[2]), "r"(a[3]), "r"(b[0]), "r"(b[1]));
}
__device__ __forceinline__ void ldm4(uint32_t* r, uint32_t addr) {
    asm volatile("ldmatrix.sync.aligned.m8n8.x4.shared.b16 {%0,%1,%2,%3}, [%4];"
        : "=r"(r[0]), "=r"(r[1]), "=r"(r[2]), "=r"(r[3]) : "r"(addr));
}

// ---------------------------------------------------------------- prepack (fused, -> fp16)
#define TOTX (BB * KK / 2)
#define TOTW (OO * KK / 2)
__global__ void __launch_bounds__(256) prepack_all(const int* __restrict__ px,
                                                   const int* __restrict__ pw) {
    int i = blockIdx.x * blockDim.x + threadIdx.x;
    const int* src;
    uint32_t* dst;
    int j;
    if (i < TOTX) { src = px; dst = (uint32_t*)g_xh; j = i; }
    else if (i < TOTX + TOTW) { src = pw; dst = (uint32_t*)g_wh; j = i - TOTX; }
    else return;
    int v = src[j];
    int lo = ((v & 15) ^ 8) - 8;
    int hi = (((v >> 4) & 15) ^ 8) - 8;
    __half2 h = __halves2half2(__int2half_rn(lo), __int2half_rn(hi));
    dst[j] = *(uint32_t*)&h;
}

// ---------------------------------------------------------------- GEMM (fp16 HMMA, ldmatrix)
// smem per stage: A rows 0..127 then B rows 0..127; row = 128 k fp16 = 256B = 16 chunks.
// chunk c of row r stored at phys = c ^ (r & 7)  (permutes within 16 chunks; conflict-free)
__global__ void __launch_bounds__(NTHREADS, 1)
gemm_kernel(const float* __restrict__ a_scale, const float* __restrict__ w_scale,
            const float* __restrict__ bias, float* __restrict__ out) {
    extern __shared__ uint8_t smem[];
    __half* s_as = (__half*)smem;                  // [32 groups][128 rows] fp16 (exact)
    __half* s_ws = (__half*)(smem + 8192);         // [32 groups][128 cols]
    uint8_t* s_data = smem + SCALE_BYTES;

    int tid = threadIdx.x, wid = tid >> 5, lane = tid & 31;
    int g8 = lane >> 2, tig = lane & 3;
    int l7 = lane & 7;
    // warp grid 4M x 4N, warp tile 32M x 32N
    int warp_m = (wid & 3) * 32;
    int warp_n = (wid >> 2) * 32;

    // ldmatrix per-lane row/parity decomposition
    int arow_off = l7 + ((lane >> 3) & 1) * 8;   // A: matrices 0/1 rows, 2/3 repeat
    int ap = lane >> 4;                          // A: chunk parity (k lo/hi half)
    int brow_off = l7 + ((lane >> 4) & 1) * 8;   // B: matrices 0/1 tile n, 2/3 tile n+1
    int bp = (lane >> 3) & 1;                    // B: chunk parity

    // supertile rasterization (8 m-tiles per group) for L2 reuse
    int bid = blockIdx.x;
    int grp = bid / (8 * NTILES);
    int rem = bid - grp * (8 * NTILES);
    int mt = grp * 8 + (rem & 7);
    int nt = rem >> 3;
    int m0 = mt * MT, n0 = nt * NT;

    // stage scales once per CTA, transposed to [group][row], fp16 (exact round-trip)
    #pragma unroll 2
    for (int i = tid; i < 4096; i += NTHREADS) {
        int g = i >> 7, r = i & 127;
        s_as[i] = __float2half_rn(__ldg(a_scale + (size_t)(m0 + r) * GG + g));
        s_ws[i] = __float2half_rn(__ldg(w_scale + (size_t)(n0 + r) * GG + g));
    }

    const uint8_t* gA = (const uint8_t*)g_xh + (size_t)m0 * KK * 2;
    const uint8_t* gB = (const uint8_t*)g_wh + (size_t)n0 * KK * 2;
    uint32_t sdata = smem_u32(s_data);

    // loader: 4096 x 16B per stage (group g_ covers k bytes [g_*256, +256))
#define LOAD_STAGE(slot, g_)                                                       \
    do {                                                                           \
        uint32_t st_ = sdata + (slot) * STAGE_BYTES;                               \
        _Pragma("unroll")                                                          \
        for (int it_ = 0; it_ < 8; it_++) {                                        \
            int j_ = tid + NTHREADS * it_;                                         \
            int r_ = (j_ >> 4) & 127;                                              \
            int c_ = j_ & 15;                                                      \
            int phys_ = c_ ^ (r_ & 7);                                             \
            uint32_t sa_ = st_ + (uint32_t)((j_ >> 11) * 32768 + r_ * 256 + phys_ * 16); \
            const uint8_t* gp_ = ((j_ >> 11) ? gB : gA) + (size_t)r_ * (KK * 2) + (g_) * 256 + c_ * 16; \
            cp16(sa_, gp_);                                                        \
        }                                                                          \
        cp_commit();                                                               \
    } while (0)

    LOAD_STAGE(0, 0);
    LOAD_STAGE(1, 1);

    float accf[2][4][4];    // running rescaled accumulator
    #pragma unroll
    for (int a = 0; a < 2; a++)
        #pragma unroll
        for (int b = 0; b < 4; b++)
            #pragma unroll
            for (int c = 0; c < 4; c++) accf[a][b][c] = 0.f;

    // precomputed smem row bases (byte offsets within stage halves)
    uint32_t aoff0 = (uint32_t)(warp_m + arow_off) * 256;
    uint32_t aoff1 = aoff0 + 16 * 256;
    uint32_t boff0 = (uint32_t)(warp_n + brow_off) * 256;
    uint32_t boff1 = boff0 + 16 * 256;

    for (int g = 0; g < GG; g++) {
        cp_wait1();
        __syncthreads();
        if (g + 2 < GG) LOAD_STAGE((g + 2) % 3, g + 2);

        uint32_t stA = sdata + (g % 3) * STAGE_BYTES;
        uint32_t stB = stA + 32768;

        float accg[2][4][4];
        #pragma unroll
        for (int a = 0; a < 2; a++)
            #pragma unroll
            for (int b = 0; b < 4; b++)
                #pragma unroll
                for (int c = 0; c < 4; c++) accg[a][b][c] = 0.f;

        // 8 k16 steps per group; k16 block ks = chunks (2ks, 2ks+1)
        #pragma unroll
        for (int ks = 0; ks < 8; ks++) {
            uint32_t pa = (uint32_t)(((2 * ks + ap) ^ l7) << 4);
            uint32_t pb = (uint32_t)(((2 * ks + bp) ^ l7) << 4);
            uint32_t af[2][4];
            ldm4(af[0], stA + aoff0 + pa);
            ldm4(af[1], stA + aoff1 + pa);
            uint32_t bt0[4], bt1[4];
            ldm4(bt0, stB + boff0 + pb);   // tiles n0,n1: {b0[0],b0[1],b1[0],b1[1]}
            ldm4(bt1, stB + boff1 + pb);   // tiles n2,n3
            #pragma unroll
            for (int m = 0; m < 2; m++) {
                mma_f16(accg[m][0], af[m], bt0);
                mma_f16(accg[m][1], af[m], bt0 + 2);
                mma_f16(accg[m][2], af[m], bt1);
                mma_f16(accg[m][3], af[m], bt1 + 2);
            }
        }

        // exact per-group rescale into running accumulator
        float rs[4], cs[8];
        #pragma unroll
        for (int m = 0; m < 2; m++) {
            int r = warp_m + m * 16 + g8;
            rs[2 * m]     = __half2float(s_as[g * 128 + r]);
            rs[2 * m + 1] = __half2float(s_as[g * 128 + r + 8]);
        }
        #pragma unroll
        for (int n = 0; n < 4; n++) {
            int c = warp_n + n * 8 + tig * 2;
            cs[2 * n]     = __half2float(s_ws[g * 128 + c]);
            cs[2 * n + 1] = __half2float(s_ws[g * 128 + c + 1]);
        }
        #pragma unroll
        for (int m = 0; m < 2; m++)
            #pragma unroll
            for (int n = 0; n < 4; n++) {
                accf[m][n][0] += accg[m][n][0] * (rs[2 * m]     * cs[2 * n]);
                accf[m][n][1] += accg[m][n][1] * (rs[2 * m]     * cs[2 * n + 1]);
                accf[m][n][2] += accg[m][n][2] * (rs[2 * m + 1] * cs[2 * n]);
                accf[m][n][3] += accg[m][n][3] * (rs[2 * m + 1] * cs[2 * n + 1]);
            }
    }

    // epilogue: emulate reference fp16 rounding, store upcast float32
    #pragma unroll
    for (int m = 0; m < 2; m++)
        #pragma unroll
        for (int n = 0; n < 4; n++) {
            int row = m0 + warp_m + m * 16 + g8;
            int col = n0 + warp_n + n * 8 + tig * 2;
            __half hb0 = __float2half_rn(__ldg(bias + col));
            __half hb1 = __float2half_rn(__ldg(bias + col + 1));
            float2 lo, hi;
            lo.x = __half2float(__hadd(__float2half_rn(accf[m][n][0]), hb0));
            lo.y = __half2float(__hadd(__float2half_rn(accf[m][n][1]), hb1));
            hi.x = __half2float(__hadd(__float2half_rn(accf[m][n][2]), hb0));
            hi.y = __half2float(__hadd(__float2half_rn(accf[m][n][3]), hb1));
            *(float2*)(out + (size_t)row * OO + col) = lo;
            *(float2*)(out + (size_t)(row + 8) * OO + col) = hi;
        }
}

// ---------------------------------------------------------------- host
extern "C" void kernel_launch(void* const* d_in, const int* in_sizes, int n_in,
                              void* d_out, int out_size) {
    const int*   x        = (const int*)d_in[0];
    const float* a_scale  = (const float*)d_in[1];   // fp16 in reference -> float32 in harness
    const int*   w_packed = (const int*)d_in[2];
    const float* w_scale  = (const float*)d_in[3];
    const float* bias     = (const float*)d_in[4];
    float*       out      = (float*)d_out;

    int tot = TOTX + TOTW;
    prepack_all<<<(tot + 255) / 256, 256>>>(x, w_packed);

    static bool attr_set = false;
    if (!attr_set) {
        cudaFuncSetAttribute(gemm_kernel, cudaFuncAttributeMaxDynamicSharedMemorySize, SMEM_TOTAL);
        attr_set = true;
    }
    gemm_kernel<<<MTILES * NTILES, NTHREADS, SMEM_TOTAL>>>(a_scale, w_scale, bias, out);
}